// round 1
// baseline (speedup 1.0000x reference)
#include <cuda_runtime.h>
#include <cuda_bf16.h>
#include <math.h>

// LocalPearsonDepthLoss:
//   inputs: pred_depth [1,4096,4096] f32, gt_depth [1,4096,4096] f32,
//           x0 [n_corr] i32, y0 [n_corr] i32, box_p (=32)
//   loss = sum_i (1 - pearson(patch_p(i), patch_g(i))) / n_corr
//
// One warp per patch. Lane l handles column l; loop over 32 rows gives a
// coalesced 128B load per image per iteration. 5 running sums -> warp shuffle
// reduce -> closed-form Pearson -> block reduce -> one atomicAdd per block.

#define W_IMG 4096
#define BOX   32
#define PATCH 1024.0f

__global__ void zero_out_kernel(float* out) {
    if (threadIdx.x == 0 && blockIdx.x == 0) out[0] = 0.0f;
}

__global__ __launch_bounds__(256) void pearson_loss_kernel(
    const float* __restrict__ pred,
    const float* __restrict__ gt,
    const int*   __restrict__ x0,
    const int*   __restrict__ y0,
    float* __restrict__ out,
    int n_corr)
{
    const int warp_global = (blockIdx.x * blockDim.x + threadIdx.x) >> 5;
    const int lane = threadIdx.x & 31;
    const int wid_in_blk = threadIdx.x >> 5;

    float contrib = 0.0f;

    if (warp_global < n_corr) {
        const int xb = x0[warp_global];
        const int yb = y0[warp_global];
        const size_t base = (size_t)xb * W_IMG + yb + lane;
        const float* __restrict__ pp = pred + base;
        const float* __restrict__ gp = gt + base;

        float sp = 0.f, sg = 0.f, spp = 0.f, sgg = 0.f, spg = 0.f;

        #pragma unroll 8
        for (int r = 0; r < BOX; r++) {
            float p = __ldg(pp + (size_t)r * W_IMG);
            float g = __ldg(gp + (size_t)r * W_IMG);
            sp  += p;
            sg  += g;
            spp = fmaf(p, p, spp);
            sgg = fmaf(g, g, sgg);
            spg = fmaf(p, g, spg);
        }

        // warp tree-reduce all 5 sums
        #pragma unroll
        for (int off = 16; off > 0; off >>= 1) {
            sp  += __shfl_xor_sync(0xffffffffu, sp,  off);
            sg  += __shfl_xor_sync(0xffffffffu, sg,  off);
            spp += __shfl_xor_sync(0xffffffffu, spp, off);
            sgg += __shfl_xor_sync(0xffffffffu, sgg, off);
            spg += __shfl_xor_sync(0xffffffffu, spg, off);
        }

        if (lane == 0) {
            const float P = PATCH;
            float mp = sp / P;
            float mg = sg / P;
            // unbiased std (ddof=1), matching torch.std
            float varp = (spp - P * mp * mp) * (1.0f / (P - 1.0f));
            float varg = (sgg - P * mg * mg) * (1.0f / (P - 1.0f));
            float stdp = sqrtf(fmaxf(varp, 0.0f)) + 1e-6f;
            float stdg = sqrtf(fmaxf(varg, 0.0f)) + 1e-6f;
            // mean of centered product (denominator P, not P-1)
            float cov = spg / P - mp * mg;
            float co = cov / (stdp * stdg);
            contrib = (1.0f - co) / (float)n_corr;
        }
    }

    // block reduce the per-warp lane0 contributions, one atomicAdd per block
    __shared__ float warp_sums[8];
    if (lane == 0) warp_sums[wid_in_blk] = contrib;
    __syncthreads();
    if (wid_in_blk == 0) {
        float v = (lane < (blockDim.x >> 5)) ? warp_sums[lane] : 0.0f;
        #pragma unroll
        for (int off = 4; off > 0; off >>= 1)
            v += __shfl_xor_sync(0xffffffffu, v, off);
        if (lane == 0) atomicAdd(out, v);
    }
}

extern "C" void kernel_launch(void* const* d_in, const int* in_sizes, int n_in,
                              void* d_out, int out_size)
{
    const float* pred = (const float*)d_in[0];
    const float* gt   = (const float*)d_in[1];
    const int*   x0   = (const int*)d_in[2];
    const int*   y0   = (const int*)d_in[3];
    float* out = (float*)d_out;

    const int n_corr = in_sizes[2];

    zero_out_kernel<<<1, 32>>>(out);

    const int threads = 256;                    // 8 warps/block
    const int warps_per_blk = threads / 32;
    const int blocks = (n_corr + warps_per_blk - 1) / warps_per_blk;
    pearson_loss_kernel<<<blocks, threads>>>(pred, gt, x0, y0, out, n_corr);
}

// round 3
// speedup vs baseline: 1.0132x; 1.0132x over previous
#include <cuda_runtime.h>
#include <cuda_bf16.h>
#include <math.h>

// LocalPearsonDepthLoss — single-kernel version.
//   One warp per patch (32x32 f32). Lane l reads column l of each row:
//   coalesced 128B per image per row. 5 running sums -> warp shuffle reduce
//   -> closed-form Pearson. Block partials go to __device__ scratch; the
//   last block (atomic counter) reduces them and writes out[0], then resets
//   the counter so the kernel is graph-replay deterministic.

#define W_IMG 4096
#define BOX   32
#define PATCH 1024.0f
#define MAX_BLOCKS 8192

__device__ float        g_partials[MAX_BLOCKS];
__device__ unsigned int g_done = 0;

__global__ __launch_bounds__(256) void pearson_loss_kernel(
    const float* __restrict__ pred,
    const float* __restrict__ gt,
    const int*   __restrict__ x0,
    const int*   __restrict__ y0,
    float* __restrict__ out,
    int n_corr)
{
    const int warp_global = (blockIdx.x * blockDim.x + threadIdx.x) >> 5;
    const int lane = threadIdx.x & 31;
    const int wid_in_blk = threadIdx.x >> 5;

    float contrib = 0.0f;

    if (warp_global < n_corr) {
        const int xb = x0[warp_global];
        const int yb = y0[warp_global];
        const size_t base = (size_t)xb * W_IMG + yb + lane;
        const float* __restrict__ pp = pred + base;
        const float* __restrict__ gp = gt + base;

        float sp = 0.f, sg = 0.f, spp = 0.f, sgg = 0.f, spg = 0.f;

        // Batch 8+8 loads into registers before consuming -> guaranteed MLP.
        #pragma unroll
        for (int rb = 0; rb < BOX / 8; rb++) {
            float pbuf[8], gbuf[8];
            #pragma unroll
            for (int i = 0; i < 8; i++)
                pbuf[i] = __ldg(pp + (size_t)(rb * 8 + i) * W_IMG);
            #pragma unroll
            for (int i = 0; i < 8; i++)
                gbuf[i] = __ldg(gp + (size_t)(rb * 8 + i) * W_IMG);
            #pragma unroll
            for (int i = 0; i < 8; i++) {
                sp  += pbuf[i];
                sg  += gbuf[i];
                spp = fmaf(pbuf[i], pbuf[i], spp);
                sgg = fmaf(gbuf[i], gbuf[i], sgg);
                spg = fmaf(pbuf[i], gbuf[i], spg);
            }
        }

        #pragma unroll
        for (int off = 16; off > 0; off >>= 1) {
            sp  += __shfl_xor_sync(0xffffffffu, sp,  off);
            sg  += __shfl_xor_sync(0xffffffffu, sg,  off);
            spp += __shfl_xor_sync(0xffffffffu, spp, off);
            sgg += __shfl_xor_sync(0xffffffffu, sgg, off);
            spg += __shfl_xor_sync(0xffffffffu, spg, off);
        }

        if (lane == 0) {
            const float P = PATCH;
            float mp = sp / P;
            float mg = sg / P;
            float varp = (spp - P * mp * mp) * (1.0f / (P - 1.0f));
            float varg = (sgg - P * mg * mg) * (1.0f / (P - 1.0f));
            float stdp = sqrtf(fmaxf(varp, 0.0f)) + 1e-6f;
            float stdg = sqrtf(fmaxf(varg, 0.0f)) + 1e-6f;
            float cov = spg / P - mp * mg;
            float co = cov / (stdp * stdg);
            contrib = (1.0f - co) / (float)n_corr;
        }
    }

    // Block reduce warp contributions (lane0 of each warp holds them).
    __shared__ float warp_sums[8];
    __shared__ bool  is_last;
    if (lane == 0) warp_sums[wid_in_blk] = contrib;
    __syncthreads();
    if (threadIdx.x == 0) {
        float bs = 0.0f;
        #pragma unroll
        for (int w = 0; w < 8; w++) bs += warp_sums[w];
        g_partials[blockIdx.x] = bs;
        __threadfence();                       // release our partial
        unsigned int old = atomicAdd(&g_done, 1u);
        is_last = (old == gridDim.x - 1);
        if (is_last) __threadfence();          // acquire all partials
    }
    __syncthreads();

    if (is_last) {
        // Final reduction over all block partials, done by the last block.
        float v = 0.0f;
        for (int i = threadIdx.x; i < gridDim.x; i += blockDim.x)
            v += g_partials[i];
        #pragma unroll
        for (int off = 16; off > 0; off >>= 1)
            v += __shfl_xor_sync(0xffffffffu, v, off);
        if (lane == 0) warp_sums[wid_in_blk] = v;
        __syncthreads();
        if (threadIdx.x == 0) {
            float total = 0.0f;
            #pragma unroll
            for (int w = 0; w < 8; w++) total += warp_sums[w];
            out[0] = total;
            g_done = 0;   // reset for next graph replay
        }
    }
}

extern "C" void kernel_launch(void* const* d_in, const int* in_sizes, int n_in,
                              void* d_out, int out_size)
{
    const float* pred = (const float*)d_in[0];
    const float* gt   = (const float*)d_in[1];
    const int*   x0   = (const int*)d_in[2];
    const int*   y0   = (const int*)d_in[3];
    float* out = (float*)d_out;

    const int n_corr = in_sizes[2];

    const int threads = 256;                    // 8 warps/block, 1 warp/patch
    const int warps_per_blk = threads / 32;
    const int blocks = (n_corr + warps_per_blk - 1) / warps_per_blk;
    pearson_loss_kernel<<<blocks, threads>>>(pred, gt, x0, y0, out, n_corr);
}